// round 9
// baseline (speedup 1.0000x reference)
#include <cuda_runtime.h>
#include <cuda_fp16.h>
#include <cstdint>
#include <math.h>

#define N_SAMP 4096
#define D      128
#define NLAY   5
#define NCU    23
#define NCP    24

#define TWO_PI 6.2831853071795864769f
#define PI_F   3.1415926535897932385f
#define C2     19.739208802178717238f     /* 2*pi^2  */
#define C3     124.02510672119926149f     /* 4*pi^3  */
#define S_CONST 8.3666002653407556e-04f   /* sqrt(0.7/1e6) */
#define KAPPA   1.1952286093343936e-03f   /* sqrt(1/7e5)   */

#define NMAIN  1024         // main CTAs: 4 samples (96 jet rows)
#define NBND   64           // boundary CTAs: 64 samples (64 value rows)
#define NCTA   (NMAIN + NBND)
#define NTHR   512

#define SROWB  272          // fp16 state/weight row stride (bytes)
#define FROWB  544          // fp32 accum row stride (bytes)

// ------- smem layout (bytes) -------
#define SM_BIN   0          // 128 f
#define SM_BO    512        // 4 f
#define SM_BH    528        // 640 f
#define SM_WIN   3088       // 512 f
#define SM_WO    5136       // 512 f
#define SM_X     7184       // 256 f
#define SM_YT    8208       // 16 f
#define SM_YC    8272       // 368 f main / 64 f red boundary / double[16][5] reduce
#define SM_LS    9744       // 16 f
#define SM_FLAG  9808       // 4 B
#define SM_W     16384      // fp16 weights: 128*272 = 34816 B
#define SM_SHI   51200      // fp16 state: 96*272 = 26112 B
#define SM_F32   51200      // fp32 accum overlay: 96*544 = 52224 B
#define SMEM_TOTAL 103424

// jet row scales (powers of 2; exact)
#define SC1  0.0625f
#define SC2  0.00390625f
#define SC3  2.44140625e-4f
#define IS1  16.0f
#define IS2  256.0f
#define IS3  4096.0f

// ------- global scratch -------
__device__ float g_xy[2*N_SAMP];
__device__ float g_zb[N_SAMP];
__device__ float g_part[NMAIN*4];
__device__ float g_tbpart[NBND];
__device__ unsigned int g_done;
__device__ __align__(16) __half g_Wt[NLAY*D*136];

// ------- PTX helpers -------
__device__ __forceinline__ uint32_t smem_u32(const void* p) {
    uint32_t a;
    asm("{ .reg .u64 t; cvta.to.shared.u64 t, %1; cvt.u32.u64 %0, t; }" : "=r"(a) : "l"(p));
    return a;
}
#define LDSM4(r, addr) \
    asm volatile("ldmatrix.sync.aligned.m8n8.x4.shared.b16 {%0,%1,%2,%3}, [%4];" \
        : "=r"((r)[0]),"=r"((r)[1]),"=r"((r)[2]),"=r"((r)[3]) : "r"(addr))
#define MMAF16(d, a, b0, b1) \
    asm volatile("mma.sync.aligned.m16n8k16.row.col.f32.f16.f16.f32 " \
        "{%0,%1,%2,%3}, {%4,%5,%6,%7}, {%8,%9}, {%0,%1,%2,%3};" \
        : "+f"((d)[0]),"+f"((d)[1]),"+f"((d)[2]),"+f"((d)[3]) \
        : "r"((a)[0]),"r"((a)[1]),"r"((a)[2]),"r"((a)[3]), "r"(b0),"r"(b1))
#define CPASYNC16(dst, src) \
    asm volatile("cp.async.cg.shared.global [%0], [%1], 16;" :: "r"(dst), "l"(src))
#define CPCOMMIT() asm volatile("cp.async.commit_group;" ::: "memory")
#define CPWAIT0()  asm volatile("cp.async.wait_group 0;" ::: "memory")

// ------- threefry2x32-20 (exact JAX) -------
__device__ __forceinline__ void tf2(uint32_t k0, uint32_t k1, uint32_t x0, uint32_t x1,
                                    uint32_t& o0, uint32_t& o1) {
    uint32_t ks2 = k0 ^ k1 ^ 0x1BD11BDAu;
    x0 += k0; x1 += k1;
#define TF_R(r) { x0 += x1; x1 = (x1 << (r)) | (x1 >> (32-(r))); x1 ^= x0; }
    TF_R(13) TF_R(15) TF_R(26) TF_R(6)
    x0 += k1;  x1 += ks2 + 1u;
    TF_R(17) TF_R(29) TF_R(16) TF_R(24)
    x0 += ks2; x1 += k0 + 2u;
    TF_R(13) TF_R(15) TF_R(26) TF_R(6)
    x0 += k0;  x1 += k1 + 3u;
    TF_R(17) TF_R(29) TF_R(16) TF_R(24)
    x0 += k1;  x1 += ks2 + 4u;
    TF_R(13) TF_R(15) TF_R(26) TF_R(6)
    x0 += ks2; x1 += k0 + 5u;
#undef TF_R
    o0 = x0; o1 = x1;
}
__device__ __forceinline__ float u01(uint32_t bits) {
    return __uint_as_float((bits >> 9) | 0x3F800000u) - 1.0f;
}

// ------- prep: weight transpose + fp16 + rng -------
__global__ void __launch_bounds__(256) pinn_prep(const float* __restrict__ Wh) {
    int b = blockIdx.x;
    if (b < 320) {
        int idx = b * 256 + threadIdx.x;
        int l = idx >> 14;
        int rem = idx & 16383;
        int n = rem >> 7, k = rem & 127;
        float v = Wh[l * 16384 + k * 128 + n];
        g_Wt[(l * 128 + n) * 136 + k] = __float2half_rn(v);
    } else {
        int i = (b - 320) * 256 + threadIdx.x;
        uint32_t a0, a1, b0, b1;
        tf2(0u, 22u, 0u, 2u, a0, a1);
        tf2(0u, 22u, 1u, 3u, b0, b1);
        uint32_t o0, o1;
        tf2(a0, b0, (uint32_t)i, (uint32_t)(i + 4096), o0, o1);
        g_xy[i]        = u01(o0);
        g_xy[i + 4096] = u01(o1);
        if (i < 2048) {
            uint32_t r0, r1;
            tf2(a1, b1, (uint32_t)i, (uint32_t)(i + 2048), r0, r1);
            g_zb[i]        = (float)(r0 & 1u);
            g_zb[i + 2048] = (float)(r1 & 1u);
        }
    }
}

// ------- activation jet propagation -------
__device__ __forceinline__ void act_prop(float z[NCU]) {
    const int p2a[9] = {0,0,0,1,1,1,2,2,3};
    const int p2b[9] = {1,2,3,1,2,3,2,3,3};
    const int t3a[9] = {1,2,3,1,2,3,1,2,3};
    const int t3b[9] = {1,1,1,2,2,2,3,3,3};
    const int s2s[4][4] = { {0,0,1,2}, {0,3,4,5}, {1,4,6,7}, {2,5,7,8} };

    float sv, cv;
    __sincosf(TWO_PI * z[0], &sv, &cv);
    float f0 = 0.5f * sv;
    float f1 = PI_F * cv;
    float f2 = -C2 * sv;
    float f3 = -C3 * cv;

    float d1[4], d2[9], d3[9];
#pragma unroll
    for (int i = 0; i < 4; i++) d1[i] = z[1+i];
#pragma unroll
    for (int p = 0; p < 9; p++) d2[p] = z[5+p];
#pragma unroll
    for (int q = 0; q < 9; q++) d3[q] = z[14+q];

    z[0] = f0;
#pragma unroll
    for (int i = 0; i < 4; i++) z[1+i] = f1 * d1[i];
#pragma unroll
    for (int p = 0; p < 9; p++)
        z[5+p] = f1 * d2[p] + f2 * d1[p2a[p]] * d1[p2b[p]];
#pragma unroll
    for (int q = 0; q < 9; q++) {
        int a = t3a[q], bq = t3b[q];
        float zbb = d2[s2s[bq][bq]];
        float zab = d2[s2s[a][bq]];
        z[14+q] = f1 * d3[q] + f2 * (d1[a]*zbb + 2.0f*d1[bq]*zab) + f3 * d1[a]*d1[bq]*d1[bq];
    }
}

__device__ __forceinline__ float coeff_scale(int c) {
    return (c == 0) ? 1.0f : (c < 5 ? SC1 : (c < 14 ? SC2 : SC3));
}
__device__ __forceinline__ float coeff_iscale(int c) {
    return (c == 0) ? 1.0f : (c < 5 ? IS1 : (c < 14 ? IS2 : IS3));
}

// ------- fp16 state writes -------
__device__ __forceinline__ void write_h1(char* sm, int r, int c, float v) {
    *(__half*)(sm + SM_SHI + r * SROWB + c * 2) = __float2half_rn(v);
}
__device__ __forceinline__ void write_h4(char* sm, int r, int c4, const float v[4]) {
    __half h0 = __float2half_rn(v[0]), h1 = __float2half_rn(v[1]);
    __half h2 = __float2half_rn(v[2]), h3 = __float2half_rn(v[3]);
    uint2 hi;
    hi.x = (uint32_t)__half_as_ushort(h0) | ((uint32_t)__half_as_ushort(h1) << 16);
    hi.y = (uint32_t)__half_as_ushort(h2) | ((uint32_t)__half_as_ushort(h3) << 16);
    *(uint2*)(sm + SM_SHI + r * SROWB + c4 * 2) = hi;
}

// ------- single-term fp16 GEMM: MT*16 rows x 16 cols per warp -------
template<int MT>
__device__ __forceinline__ void gemm1(uint32_t smb, int row0, int col0, int lane,
                                      float acc[MT][2][4]) {
#pragma unroll
    for (int i = 0; i < MT; i++)
#pragma unroll
        for (int j = 0; j < 2; j++)
#pragma unroll
            for (int q = 0; q < 4; q++) acc[i][j][q] = 0.0f;

    int rA = (lane & 7) + ((lane >> 3) & 1) * 8;
    int kA = (lane >> 4) * 8;
    int nB = (lane & 7) + ((lane >> 4) & 1) * 8;
    int kB = ((lane >> 3) & 1) * 8;

    uint32_t aH0 = smb + SM_SHI + (uint32_t)(row0 + rA) * SROWB + kA * 2;
    uint32_t bH0 = smb + SM_W   + (uint32_t)(col0 + nB) * SROWB + kB * 2;

#pragma unroll
    for (int kc = 0; kc < 8; kc++) {
        uint32_t ko = kc * 32;
        uint32_t aH[MT][4], bH[4];
#pragma unroll
        for (int i = 0; i < MT; i++)
            LDSM4(aH[i], aH0 + (uint32_t)(i * 16) * SROWB + ko);
        LDSM4(bH, bH0 + ko);
#pragma unroll
        for (int i = 0; i < MT; i++)
#pragma unroll
            for (int j2 = 0; j2 < 2; j2++)
                MMAF16(acc[i][j2], aH[i], bH[j2*2], bH[j2*2+1]);
    }
}

template<int MT>
__device__ __forceinline__ void store_accf(char* sm, int row0, int col0, int lane,
                                           float acc[MT][2][4]) {
    int g = lane >> 2, t = lane & 3;
#pragma unroll
    for (int i = 0; i < MT; i++)
#pragma unroll
        for (int j2 = 0; j2 < 2; j2++) {
            int r = row0 + i * 16 + g;
            int c = col0 + j2 * 8 + 2 * t;
            *(float2*)(sm + SM_F32 + r * FROWB + c * 4) = make_float2(acc[i][j2][0], acc[i][j2][1]);
            *(float2*)(sm + SM_F32 + (r + 8) * FROWB + c * 4) = make_float2(acc[i][j2][2], acc[i][j2][3]);
        }
}

__device__ __forceinline__ void stage_weights(char* sm, int tid, int l) {
    const char* src = (const char*)g_Wt + l * 34816;
    uint32_t dW = smem_u32(sm + SM_W);
    for (int i = tid * 16; i < 34816; i += NTHR * 16)
        CPASYNC16(dW + i, src + i);
    CPCOMMIT();
}

// ------- fused tensor-core kernel (2 CTAs/SM, 512 threads) -------
__global__ void __launch_bounds__(NTHR, 2)
pinn_tc(const float* __restrict__ inputs, const float* __restrict__ y_true,
        const float* __restrict__ Win, const float* __restrict__ bin,
        const float* __restrict__ bh,  const float* __restrict__ Wo,
        const float* __restrict__ bo,  float* __restrict__ out)
{
    extern __shared__ char sm[];
    uint32_t smb = smem_u32(sm);
    int tid = threadIdx.x;
    int bid = blockIdx.x;
    bool is_b = (bid >= NMAIN);

    float* s_bin = (float*)(sm + SM_BIN);
    float* s_bo  = (float*)(sm + SM_BO);
    float* s_bh  = (float*)(sm + SM_BH);
    float* s_Win = (float*)(sm + SM_WIN);
    float* s_Wo  = (float*)(sm + SM_WO);
    float* s_x   = (float*)(sm + SM_X);
    float* s_yt  = (float*)(sm + SM_YT);
    float* s_yc  = (float*)(sm + SM_YC);
    float* s_red = (float*)(sm + SM_YC);
    float* s_ls  = (float*)(sm + SM_LS);

    // ---- prologue ----
    if (tid < 128) s_bin[tid] = bin[tid];
    for (int i = tid; i < 640; i += NTHR) s_bh[i] = bh[i];
    if (tid < 512) { s_Win[tid] = Win[tid]; s_Wo[tid] = Wo[tid]; }
    if (tid < 4) s_bo[tid] = bo[tid];
    if (!is_b) {
        if (tid < 16) { s_x[tid] = inputs[bid*16 + tid]; s_yt[tid] = y_true[bid*16 + tid]; }
    } else {
        int gs0 = (bid - NMAIN) * 64;
        if (tid < 64) {
            int gs = gs0 + tid;
            s_x[tid*4+0] = inputs[gs*4];
            s_x[tid*4+1] = g_xy[2*gs];
            s_x[tid*4+2] = g_xy[2*gs+1];
            s_x[tid*4+3] = g_zb[gs];
        }
    }
    stage_weights(sm, tid, 0);
    __syncthreads();

    int lane = tid & 31;
    int w = tid >> 5;                 // 0..15
    int wm = w >> 3, wn = w & 7;
    int col0 = wn * 16;

    // ---- input layer ----
    if (!is_b) {
        int s = tid >> 7;             // sample 0..3
        int nn = tid & 127;           // neuron
        float z[NCU];
        z[0] = s_bin[nn] + s_x[s*4]*s_Win[nn] + s_x[s*4+1]*s_Win[128+nn]
             + s_x[s*4+2]*s_Win[256+nn] + s_x[s*4+3]*s_Win[384+nn];
        z[1] = s_Win[nn]; z[2] = s_Win[128+nn]; z[3] = s_Win[256+nn]; z[4] = s_Win[384+nn];
#pragma unroll
        for (int c = 5; c < NCU; c++) z[c] = 0.0f;
        act_prop(z);
#pragma unroll
        for (int c = 0; c < NCU; c++) write_h1(sm, s*NCP + c, nn, z[c] * coeff_scale(c));
        write_h1(sm, s*NCP + 23, nn, 0.0f);
    } else {
        int s = tid >> 3;             // sample 0..63
        int q = tid & 7;              // 16-neuron group
        float x0 = s_x[s*4], x1 = s_x[s*4+1], x2 = s_x[s*4+2], x3 = s_x[s*4+3];
#pragma unroll
        for (int i = 0; i < 4; i++) {
            float v[4];
#pragma unroll
            for (int j = 0; j < 4; j++) {
                int nn = q*16 + i*4 + j;
                float z = s_bin[nn] + x0*s_Win[nn] + x1*s_Win[128+nn]
                        + x2*s_Win[256+nn] + x3*s_Win[384+nn];
                v[j] = 0.5f * __sinf(TWO_PI * z);
            }
            write_h4(sm, s, q*16 + i*4, v);
        }
    }

    // ---- hidden layers ----
    for (int l = 0; l < NLAY; l++) {
        CPWAIT0();
        __syncthreads();

        if (!is_b) {
            float acc[3][2][4];
            gemm1<3>(smb, wm * 48, col0, lane, acc);
            __syncthreads();
            if (l < NLAY-1) stage_weights(sm, tid, l + 1);
            store_accf<3>(sm, wm * 48, col0, lane, acc);
        } else {
            float acc[2][2][4];
            gemm1<2>(smb, wm * 32, col0, lane, acc);
            __syncthreads();
            if (l < NLAY-1) stage_weights(sm, tid, l + 1);
            store_accf<2>(sm, wm * 32, col0, lane, acc);
        }
        __syncthreads();

        // ---- activation ----
        if (!is_b) {
            int s = tid >> 7;
            int nn = tid & 127;
            float z[NCU];
#pragma unroll
            for (int c = 0; c < NCU; c++)
                z[c] = *(const float*)(sm + SM_F32 + (s*NCP + c) * FROWB + nn * 4) * coeff_iscale(c);
            z[0] += s_bh[l*128 + nn];
            act_prop(z);
            if (l == NLAY-1) {
#pragma unroll
                for (int c = 0; c < NCU; c++)
                    *(float*)(sm + SM_F32 + (s*NCP + c) * FROWB + nn * 4) = z[c];
            } else {
                __syncthreads();   // all f32 reads done before fp16 overwrite
#pragma unroll
                for (int c = 0; c < NCU; c++) write_h1(sm, s*NCP + c, nn, z[c] * coeff_scale(c));
                write_h1(sm, s*NCP + 23, nn, 0.0f);
            }
        } else {
            int s = tid >> 3;
            int q = tid & 7;
            float zc[4][4];
#pragma unroll
            for (int i = 0; i < 4; i++) {
                float4 t4 = *(const float4*)(sm + SM_F32 + s * FROWB + (q*16 + i*4) * 4);
                zc[i][0] = t4.x; zc[i][1] = t4.y; zc[i][2] = t4.z; zc[i][3] = t4.w;
            }
#pragma unroll
            for (int i = 0; i < 4; i++)
#pragma unroll
                for (int j = 0; j < 4; j++)
                    zc[i][j] = 0.5f * __sinf(TWO_PI * (zc[i][j] + s_bh[l*128 + q*16 + i*4 + j]));
            if (l == NLAY-1) {
#pragma unroll
                for (int i = 0; i < 4; i++)
                    *(float4*)(sm + SM_F32 + s * FROWB + (q*16 + i*4) * 4)
                        = make_float4(zc[i][0], zc[i][1], zc[i][2], zc[i][3]);
            } else {
                __syncthreads();
#pragma unroll
                for (int i = 0; i < 4; i++) write_h4(sm, s, q*16 + i*4, zc[i]);
            }
        }
    }
    __syncthreads();

    // ---- output layer + losses ----
    if (!is_b) {
        if (tid < 384) {
            int row = tid >> 2, o = tid & 3;
            int s = row / NCP, c = row % NCP;
            if (c < NCU) {
                float a = 0.0f;
                const float* hr = (const float*)(sm + SM_F32 + row * FROWB);
                for (int k = 0; k < D; k++)
                    a += hr[k] * s_Wo[k*4 + o];
                if (c == 0) a += s_bo[o];
                s_yc[(s*NCU + c)*4 + o] = a;
            }
        }
        __syncthreads();
        if (tid < 4) {
            const int s = tid;
            const int s2c[4][4] = { {0,5,6,7}, {5,8,9,10}, {6,9,11,12}, {7,10,12,13} };
            auto YC = [&](int c, int o) { return s_yc[(s*NCU + c)*4 + o]; };
            auto Hc = [&](int o, int i, int j) { return YC(s2c[i][j], o); };
            auto Gc = [&](int o, int a, int b2) { return YC(14 + (b2-1)*3 + (a-1), o); };
            auto J  = [&](int o, int i) { return YC(1+i, o); };

            float u = YC(0,0), v = YC(0,1), wv = YC(0,2);
            float u_x=J(0,1), u_y=J(0,2), u_z=J(0,3);
            float v_x=J(1,1), v_y=J(1,2), v_z=J(1,3);
            float w_x=J(2,1), w_y=J(2,2), w_z=J(2,3);
            float T_t=J(3,0), T_x=J(3,1), T_y=J(3,2), T_z=J(3,3);

            float om_x = w_y - v_z, om_y = u_z - w_x, om_z = v_x - u_y;

            float NSE_u = Hc(2,2,0) - Hc(1,3,0)
                        + u*(Hc(2,2,1)-Hc(1,3,1)) + v*(Hc(2,2,2)-Hc(1,3,2)) + wv*(Hc(2,2,3)-Hc(1,3,3))
                        - om_x*u_x - om_y*u_y - om_z*u_z
                        - S_CONST*( Gc(2,2,1)-Gc(1,3,1) + Gc(2,2,2)-Gc(1,3,2) + Gc(2,2,3)-Gc(1,3,3) )
                        - T_y;
            float NSE_v = Hc(0,3,0) - Hc(2,1,0)
                        + u*(Hc(0,3,1)-Hc(2,1,1)) + v*(Hc(0,3,2)-Hc(2,1,2)) + wv*(Hc(0,3,3)-Hc(2,1,3))
                        - om_x*v_x - om_y*v_y - om_z*v_z
                        - S_CONST*( Gc(0,3,1)-Gc(2,1,1) + Gc(0,3,2)-Gc(2,1,2) + Gc(0,3,3)-Gc(2,1,3) )
                        + T_x;
            float NSE_w = Hc(1,1,0) - Hc(0,2,0)
                        + u*(Hc(1,1,1)-Hc(0,2,1)) + v*(Hc(1,1,2)-Hc(0,2,2)) + wv*(Hc(1,1,3)-Hc(0,2,3))
                        - om_x*w_x - om_y*w_y - om_z*w_z
                        - S_CONST*( Gc(1,1,1)-Gc(0,2,1) + Gc(1,1,2)-Gc(0,2,2) + Gc(1,1,3)-Gc(0,2,3) );
            float EE = T_t + u*T_x + v*T_y + wv*T_z
                     - KAPPA*( Hc(3,1,1) + Hc(3,2,2) + Hc(3,3,3) );

            float ld = 0.0f;
#pragma unroll
            for (int o = 0; o < 3; o++) {
                float dd = YC(0,o) - s_yt[s*4 + o];
                ld += dd*dd;
            }
            float conti = u_x + v_y + w_z;
            s_ls[s*4+0] = ld;
            s_ls[s*4+1] = conti*conti;
            s_ls[s*4+2] = NSE_u*NSE_u + NSE_v*NSE_v + NSE_w*NSE_w;
            s_ls[s*4+3] = EE*EE;
        }
        __syncthreads();
        if (tid == 0) {
            float a0=0, a1=0, a2=0, a3=0;
            for (int s = 0; s < 4; s++) {
                a0 += s_ls[s*4+0]; a1 += s_ls[s*4+1];
                a2 += s_ls[s*4+2]; a3 += s_ls[s*4+3];
            }
            g_part[bid*4+0] = a0; g_part[bid*4+1] = a1;
            g_part[bid*4+2] = a2; g_part[bid*4+3] = a3;
        }
    } else {
        if (tid < 64) {
            float acc = 0.0f;
            const float* hr = (const float*)(sm + SM_F32 + tid * FROWB);
            for (int k = 0; k < D; k++)
                acc += hr[k] * s_Wo[k*4+3];
            float T = acc + s_bo[3];
            float Tt = (s_x[tid*4+3] == 0.0f) ? 0.5f : -0.5f;
            float dd = Tt - T;
            s_red[tid] = dd * dd;
        }
        __syncthreads();
        if (tid == 0) {
            float a = 0.0f;
            for (int i = 0; i < 64; i++) a += s_red[i];
            g_tbpart[bid - NMAIN] = a;
        }
    }

    // ---- last-CTA final reduction ----
    __syncthreads();
    if (tid == 0) {
        __threadfence();
        unsigned int old = atomicAdd(&g_done, 1u);
        *(unsigned int*)(sm + SM_FLAG) = (old == NCTA - 1) ? 1u : 0u;
    }
    __syncthreads();
    if (*(volatile unsigned int*)(sm + SM_FLAG)) {
        double v[5] = {0, 0, 0, 0, 0};
        for (int i = tid; i < NMAIN; i += NTHR) {
            v[0] += (double)g_part[i*4+0];
            v[1] += (double)g_part[i*4+1];
            v[2] += (double)g_part[i*4+2];
            v[3] += (double)g_part[i*4+3];
        }
        if (tid < NBND) v[4] = (double)g_tbpart[tid];
#pragma unroll
        for (int o = 16; o; o >>= 1)
#pragma unroll
            for (int q = 0; q < 5; q++)
                v[q] += __shfl_down_sync(0xFFFFFFFFu, v[q], o);
        double* sacc = (double*)(sm + SM_YC);
        if (lane == 0)
#pragma unroll
            for (int q = 0; q < 5; q++) sacc[w*5 + q] = v[q];
        __syncthreads();
        if (tid == 0) {
            double s5[5] = {0, 0, 0, 0, 0};
            for (int ww = 0; ww < 16; ww++)
#pragma unroll
                for (int q = 0; q < 5; q++) s5[q] += sacc[ww*5 + q];
            double Nf = (double)N_SAMP;
            out[0] = (float)(s5[0]/(3.0*Nf) + s5[1]/Nf + s5[2]/(3.0*Nf) + s5[3]/Nf + s5[4]/Nf);
            g_done = 0;   // reset for next graph replay
        }
    }
}

// ------- launch -------
extern "C" void kernel_launch(void* const* d_in, const int* in_sizes, int n_in,
                              void* d_out, int out_size) {
    const float* inputs = (const float*)d_in[0];
    const float* y_true = (const float*)d_in[1];
    const float* Win    = (const float*)d_in[2];
    const float* bin    = (const float*)d_in[3];
    const float* Wh     = (const float*)d_in[4];
    const float* bh     = (const float*)d_in[5];
    const float* Wo     = (const float*)d_in[6];
    const float* bo     = (const float*)d_in[7];
    float* out = (float*)d_out;

    cudaFuncSetAttribute(pinn_tc, cudaFuncAttributeMaxDynamicSharedMemorySize, SMEM_TOTAL);

    pinn_prep<<<336, 256>>>(Wh);
    pinn_tc<<<NCTA, NTHR, SMEM_TOTAL>>>(inputs, y_true, Win, bin, bh, Wo, bo, out);
}

// round 13
// speedup vs baseline: 1.2009x; 1.2009x over previous
#include <cuda_runtime.h>
#include <cuda_fp16.h>
#include <cstdint>
#include <math.h>

#define N_SAMP 4096
#define D      128
#define NLAY   5
#define NCU    23
#define NCP    24

#define TWO_PI 6.2831853071795864769f
#define PI_F   3.1415926535897932385f
#define C2     19.739208802178717238f     /* 2*pi^2  */
#define C3     124.02510672119926149f     /* 4*pi^3  */
#define S_CONST 8.3666002653407556e-04f   /* sqrt(0.7/1e6) */
#define KAPPA   1.1952286093343936e-03f   /* sqrt(1/7e5)   */

#define NMAIN  1024         // main CTAs: 4 samples (96 jet rows)
#define NBND   64           // boundary CTAs: 64 samples (64 value rows)
#define NCTA   (NMAIN + NBND)
#define NTHR   256

#define SROWB  272          // fp16 state/weight row stride (bytes)
#define FROWB  544          // fp32 accum row stride (bytes)

// ------- smem layout (bytes) -------
#define SM_BIN   0          // 128 f
#define SM_BO    512        // 4 f
#define SM_BH    528        // 640 f
#define SM_WIN   3088       // 512 f
#define SM_WO    5136       // 512 f
#define SM_X     7184       // 256 f
#define SM_YT    8208       // 16 f
#define SM_YC    8272       // 368 f main / 64 f red boundary / double[8][5] reduce
#define SM_LS    9744       // 16 f
#define SM_FLAG  9808       // 4 B
#define SM_W     16384      // fp16 weights: 128*272 = 34816 B
#define SM_SHI   51200      // fp16 state: 96*272 = 26112 B
#define SM_F32   51200      // fp32 accum overlay: 96*544 = 52224 B
#define SMEM_TOTAL 103424

// jet row scales (powers of 2; exact)
#define SC1  0.0625f
#define SC2  0.00390625f
#define SC3  2.44140625e-4f
#define IS1  16.0f
#define IS2  256.0f
#define IS3  4096.0f

// ------- global scratch -------
__device__ float g_xy[2*N_SAMP];
__device__ float g_zb[N_SAMP];
__device__ float g_part[NMAIN*4];
__device__ float g_tbpart[NBND];
__device__ unsigned int g_done;
__device__ __align__(16) __half g_Wt[NLAY*D*136];

// ------- PTX helpers -------
__device__ __forceinline__ uint32_t smem_u32(const void* p) {
    uint32_t a;
    asm("{ .reg .u64 t; cvta.to.shared.u64 t, %1; cvt.u32.u64 %0, t; }" : "=r"(a) : "l"(p));
    return a;
}
#define LDSM4(r, addr) \
    asm volatile("ldmatrix.sync.aligned.m8n8.x4.shared.b16 {%0,%1,%2,%3}, [%4];" \
        : "=r"((r)[0]),"=r"((r)[1]),"=r"((r)[2]),"=r"((r)[3]) : "r"(addr))
#define MMAF16(d, a, b0, b1) \
    asm volatile("mma.sync.aligned.m16n8k16.row.col.f32.f16.f16.f32 " \
        "{%0,%1,%2,%3}, {%4,%5,%6,%7}, {%8,%9}, {%0,%1,%2,%3};" \
        : "+f"((d)[0]),"+f"((d)[1]),"+f"((d)[2]),"+f"((d)[3]) \
        : "r"((a)[0]),"r"((a)[1]),"r"((a)[2]),"r"((a)[3]), "r"(b0),"r"(b1))
#define CPASYNC16(dst, src) \
    asm volatile("cp.async.cg.shared.global [%0], [%1], 16;" :: "r"(dst), "l"(src))
#define CPCOMMIT() asm volatile("cp.async.commit_group;" ::: "memory")
#define CPWAIT0()  asm volatile("cp.async.wait_group 0;" ::: "memory")

// ------- threefry2x32-20 (exact JAX) -------
__device__ __forceinline__ void tf2(uint32_t k0, uint32_t k1, uint32_t x0, uint32_t x1,
                                    uint32_t& o0, uint32_t& o1) {
    uint32_t ks2 = k0 ^ k1 ^ 0x1BD11BDAu;
    x0 += k0; x1 += k1;
#define TF_R(r) { x0 += x1; x1 = (x1 << (r)) | (x1 >> (32-(r))); x1 ^= x0; }
    TF_R(13) TF_R(15) TF_R(26) TF_R(6)
    x0 += k1;  x1 += ks2 + 1u;
    TF_R(17) TF_R(29) TF_R(16) TF_R(24)
    x0 += ks2; x1 += k0 + 2u;
    TF_R(13) TF_R(15) TF_R(26) TF_R(6)
    x0 += k0;  x1 += k1 + 3u;
    TF_R(17) TF_R(29) TF_R(16) TF_R(24)
    x0 += k1;  x1 += ks2 + 4u;
    TF_R(13) TF_R(15) TF_R(26) TF_R(6)
    x0 += ks2; x1 += k0 + 5u;
#undef TF_R
    o0 = x0; o1 = x1;
}
__device__ __forceinline__ float u01(uint32_t bits) {
    return __uint_as_float((bits >> 9) | 0x3F800000u) - 1.0f;
}

// ------- prep: weight transpose + fp16 + rng -------
__global__ void __launch_bounds__(256) pinn_prep(const float* __restrict__ Wh) {
    int b = blockIdx.x;
    if (b < 320) {
        int idx = b * 256 + threadIdx.x;
        int l = idx >> 14;
        int rem = idx & 16383;
        int n = rem >> 7, k = rem & 127;
        float v = Wh[l * 16384 + k * 128 + n];
        g_Wt[(l * 128 + n) * 136 + k] = __float2half_rn(v);
    } else {
        int i = (b - 320) * 256 + threadIdx.x;
        uint32_t a0, a1, b0, b1;
        tf2(0u, 22u, 0u, 2u, a0, a1);
        tf2(0u, 22u, 1u, 3u, b0, b1);
        uint32_t o0, o1;
        tf2(a0, b0, (uint32_t)i, (uint32_t)(i + 4096), o0, o1);
        g_xy[i]        = u01(o0);
        g_xy[i + 4096] = u01(o1);
        if (i < 2048) {
            uint32_t r0, r1;
            tf2(a1, b1, (uint32_t)i, (uint32_t)(i + 2048), r0, r1);
            g_zb[i]        = (float)(r0 & 1u);
            g_zb[i + 2048] = (float)(r1 & 1u);
        }
    }
}

// ------- activation jet propagation -------
__device__ __forceinline__ void act_prop(float z[NCU]) {
    const int p2a[9] = {0,0,0,1,1,1,2,2,3};
    const int p2b[9] = {1,2,3,1,2,3,2,3,3};
    const int t3a[9] = {1,2,3,1,2,3,1,2,3};
    const int t3b[9] = {1,1,1,2,2,2,3,3,3};
    const int s2s[4][4] = { {0,0,1,2}, {0,3,4,5}, {1,4,6,7}, {2,5,7,8} };

    float sv, cv;
    __sincosf(TWO_PI * z[0], &sv, &cv);
    float f0 = 0.5f * sv;
    float f1 = PI_F * cv;
    float f2 = -C2 * sv;
    float f3 = -C3 * cv;

    float d1[4], d2[9], d3[9];
#pragma unroll
    for (int i = 0; i < 4; i++) d1[i] = z[1+i];
#pragma unroll
    for (int p = 0; p < 9; p++) d2[p] = z[5+p];
#pragma unroll
    for (int q = 0; q < 9; q++) d3[q] = z[14+q];

    z[0] = f0;
#pragma unroll
    for (int i = 0; i < 4; i++) z[1+i] = f1 * d1[i];
#pragma unroll
    for (int p = 0; p < 9; p++)
        z[5+p] = f1 * d2[p] + f2 * d1[p2a[p]] * d1[p2b[p]];
#pragma unroll
    for (int q = 0; q < 9; q++) {
        int a = t3a[q], bq = t3b[q];
        float zbb = d2[s2s[bq][bq]];
        float zab = d2[s2s[a][bq]];
        z[14+q] = f1 * d3[q] + f2 * (d1[a]*zbb + 2.0f*d1[bq]*zab) + f3 * d1[a]*d1[bq]*d1[bq];
    }
}

__device__ __forceinline__ float coeff_scale(int c) {
    return (c == 0) ? 1.0f : (c < 5 ? SC1 : (c < 14 ? SC2 : SC3));
}
__device__ __forceinline__ float coeff_iscale(int c) {
    return (c == 0) ? 1.0f : (c < 5 ? IS1 : (c < 14 ? IS2 : IS3));
}

// ------- fp16 state writes -------
__device__ __forceinline__ void write_h2(char* sm, int r, int c2, float v0, float v1) {
    __half h0 = __float2half_rn(v0), h1 = __float2half_rn(v1);
    uint32_t hi = (uint32_t)__half_as_ushort(h0) | ((uint32_t)__half_as_ushort(h1) << 16);
    *(uint32_t*)(sm + SM_SHI + r * SROWB + c2 * 2) = hi;
}
__device__ __forceinline__ void write_h4(char* sm, int r, int c4, const float v[4]) {
    __half h0 = __float2half_rn(v[0]), h1 = __float2half_rn(v[1]);
    __half h2 = __float2half_rn(v[2]), h3 = __float2half_rn(v[3]);
    uint2 hi;
    hi.x = (uint32_t)__half_as_ushort(h0) | ((uint32_t)__half_as_ushort(h1) << 16);
    hi.y = (uint32_t)__half_as_ushort(h2) | ((uint32_t)__half_as_ushort(h3) << 16);
    *(uint2*)(sm + SM_SHI + r * SROWB + c4 * 2) = hi;
}

// ------- single-term fp16 GEMM: MT*16 rows x 32 cols per warp -------
template<int MT>
__device__ __forceinline__ void gemm1(uint32_t smb, int row0, int col0, int lane,
                                      float acc[MT][4][4]) {
#pragma unroll
    for (int i = 0; i < MT; i++)
#pragma unroll
        for (int j = 0; j < 4; j++)
#pragma unroll
            for (int q = 0; q < 4; q++) acc[i][j][q] = 0.0f;

    int rA = (lane & 7) + ((lane >> 3) & 1) * 8;
    int kA = (lane >> 4) * 8;
    int nB = (lane & 7) + ((lane >> 4) & 1) * 8;
    int kB = ((lane >> 3) & 1) * 8;

    uint32_t aH0 = smb + SM_SHI + (uint32_t)(row0 + rA) * SROWB + kA * 2;
    uint32_t bH0 = smb + SM_W   + (uint32_t)(col0 + nB) * SROWB + kB * 2;

#pragma unroll
    for (int kc = 0; kc < 8; kc++) {
        uint32_t ko = kc * 32;
        uint32_t aH[MT][4], bH[2][4];
#pragma unroll
        for (int i = 0; i < MT; i++)
            LDSM4(aH[i], aH0 + (uint32_t)(i * 16) * SROWB + ko);
#pragma unroll
        for (int j = 0; j < 2; j++)
            LDSM4(bH[j], bH0 + (uint32_t)(j * 16) * SROWB + ko);
#pragma unroll
        for (int i = 0; i < MT; i++)
#pragma unroll
            for (int j2 = 0; j2 < 4; j2++) {
                const uint32_t* bh = &bH[j2 >> 1][(j2 & 1) * 2];
                MMAF16(acc[i][j2], aH[i], bh[0], bh[1]);
            }
    }
}

// store accumulators as fp32 into overlay region (warp-private rectangle)
template<int MT>
__device__ __forceinline__ void store_accf(char* sm, int row0, int col0, int lane,
                                           float acc[MT][4][4]) {
    int g = lane >> 2, t = lane & 3;
#pragma unroll
    for (int i = 0; i < MT; i++)
#pragma unroll
        for (int j2 = 0; j2 < 4; j2++) {
            int r = row0 + i * 16 + g;
            int c = col0 + j2 * 8 + 2 * t;
            *(float2*)(sm + SM_F32 + r * FROWB + c * 4) = make_float2(acc[i][j2][0], acc[i][j2][1]);
            *(float2*)(sm + SM_F32 + (r + 8) * FROWB + c * 4) = make_float2(acc[i][j2][2], acc[i][j2][3]);
        }
}

__device__ __forceinline__ void stage_weights(char* sm, int tid, int l) {
    const char* src = (const char*)g_Wt + l * 34816;
    uint32_t dW = smem_u32(sm + SM_W);
    for (int i = tid * 16; i < 34816; i += NTHR * 16)
        CPASYNC16(dW + i, src + i);
    CPCOMMIT();
}

// ------- fused tensor-core kernel (2 CTAs/SM) -------
__global__ void __launch_bounds__(NTHR, 2)
pinn_tc(const float* __restrict__ inputs, const float* __restrict__ y_true,
        const float* __restrict__ Win, const float* __restrict__ bin,
        const float* __restrict__ bh,  const float* __restrict__ Wo,
        const float* __restrict__ bo,  float* __restrict__ out)
{
    extern __shared__ char sm[];
    uint32_t smb = smem_u32(sm);
    int tid = threadIdx.x;
    int bid = blockIdx.x;
    bool is_b = (bid >= NMAIN);

    float* s_bin = (float*)(sm + SM_BIN);
    float* s_bo  = (float*)(sm + SM_BO);
    float* s_bh  = (float*)(sm + SM_BH);
    float* s_Win = (float*)(sm + SM_WIN);
    float* s_Wo  = (float*)(sm + SM_WO);
    float* s_x   = (float*)(sm + SM_X);
    float* s_yt  = (float*)(sm + SM_YT);
    float* s_yc  = (float*)(sm + SM_YC);
    float* s_red = (float*)(sm + SM_YC);
    float* s_ls  = (float*)(sm + SM_LS);

    // ---- prologue ----
    if (tid < 128) s_bin[tid] = bin[tid];
    for (int i = tid; i < 640; i += NTHR) s_bh[i] = bh[i];
    for (int i = tid; i < 512; i += NTHR) { s_Win[i] = Win[i]; s_Wo[i] = Wo[i]; }
    if (tid < 4) s_bo[tid] = bo[tid];
    if (!is_b) {
        if (tid < 16) { s_x[tid] = inputs[bid*16 + tid]; s_yt[tid] = y_true[bid*16 + tid]; }
    } else {
        int gs0 = (bid - NMAIN) * 64;
        if (tid < 64) {
            int gs = gs0 + tid;
            s_x[tid*4+0] = inputs[gs*4];
            s_x[tid*4+1] = g_xy[2*gs];
            s_x[tid*4+2] = g_xy[2*gs+1];
            s_x[tid*4+3] = g_zb[gs];
        }
    }
    stage_weights(sm, tid, 0);
    __syncthreads();

    int lane = tid & 31;
    int w = tid >> 5;                 // 0..7
    int wm = w >> 2, wn = w & 3;
    int col0 = wn * 32;

    // ---- input layer ----
    if (!is_b) {
        int s = tid >> 6;             // sample 0..3
        int c2 = (tid & 63) * 2;      // 2 neurons
        float zc[NCU][2];
#pragma unroll
        for (int n = 0; n < 2; n++) {
            int nn = c2 + n;
            float z[NCU];
            z[0] = s_bin[nn] + s_x[s*4]*s_Win[nn] + s_x[s*4+1]*s_Win[128+nn]
                 + s_x[s*4+2]*s_Win[256+nn] + s_x[s*4+3]*s_Win[384+nn];
            z[1] = s_Win[nn]; z[2] = s_Win[128+nn]; z[3] = s_Win[256+nn]; z[4] = s_Win[384+nn];
#pragma unroll
            for (int c = 5; c < NCU; c++) z[c] = 0.0f;
            act_prop(z);
#pragma unroll
            for (int c = 0; c < NCU; c++) zc[c][n] = z[c] * coeff_scale(c);
        }
#pragma unroll
        for (int c = 0; c < NCU; c++) write_h2(sm, s*NCP + c, c2, zc[c][0], zc[c][1]);
        write_h2(sm, s*NCP + 23, c2, 0.0f, 0.0f);
    } else {
        int s = tid >> 2;             // sample 0..63
        int q = tid & 3;              // 32-neuron group
        float x0 = s_x[s*4], x1 = s_x[s*4+1], x2 = s_x[s*4+2], x3 = s_x[s*4+3];
#pragma unroll
        for (int i = 0; i < 16; i++) {
            int nn = q*32 + i*2;
            float v0, v1;
            v0 = 0.5f * __sinf(TWO_PI * (s_bin[nn] + x0*s_Win[nn] + x1*s_Win[128+nn]
                 + x2*s_Win[256+nn] + x3*s_Win[384+nn]));
            v1 = 0.5f * __sinf(TWO_PI * (s_bin[nn+1] + x0*s_Win[nn+1] + x1*s_Win[128+nn+1]
                 + x2*s_Win[256+nn+1] + x3*s_Win[384+nn+1]));
            write_h2(sm, s, nn, v0, v1);
        }
    }

    // ---- hidden layers ----
    for (int l = 0; l < NLAY; l++) {
        CPWAIT0();
        __syncthreads();              // barrier 1: weights + state visible

        if (!is_b) {
            float acc[3][4][4];
            gemm1<3>(smb, wm * 48, col0, lane, acc);
            __syncthreads();          // barrier 2: all gemm reads done
            if (l < NLAY-1) stage_weights(sm, tid, l + 1);
            store_accf<3>(sm, wm * 48, col0, lane, acc);
            __syncwarp();             // warp-private store -> act handoff

            // warp-private activation: 2 samples x 32 neurons of this warp's tile
            int s_local = lane >> 4;
            int nn = col0 + (lane & 15) * 2;
            int rbase = wm * 48 + s_local * 24;
            float zA[NCU], zB[NCU];
#pragma unroll
            for (int c = 0; c < NCU; c++) {
                float2 t2 = *(const float2*)(sm + SM_F32 + (rbase + c) * FROWB + nn * 4);
                float isv = coeff_iscale(c);
                zA[c] = t2.x * isv;
                zB[c] = t2.y * isv;
            }
            zA[0] += s_bh[l*128 + nn];
            zB[0] += s_bh[l*128 + nn + 1];
            act_prop(zA);
            act_prop(zB);
            if (l == NLAY-1) {
                // write true fp32 values in place (thread-private)
#pragma unroll
                for (int c = 0; c < NCU; c++)
                    *(float2*)(sm + SM_F32 + (rbase + c) * FROWB + nn * 4)
                        = make_float2(zA[c], zB[c]);
            } else {
                __syncthreads();      // all fp32 reads done before fp16 overwrite
#pragma unroll
                for (int c = 0; c < NCU; c++)
                    write_h2(sm, rbase + c, nn, zA[c]*coeff_scale(c), zB[c]*coeff_scale(c));
                write_h2(sm, rbase + 23, nn, 0.0f, 0.0f);
            }
        } else {
            float acc[2][4][4];
            gemm1<2>(smb, wm * 32, col0, lane, acc);
            __syncthreads();
            if (l < NLAY-1) stage_weights(sm, tid, l + 1);
            store_accf<2>(sm, wm * 32, col0, lane, acc);
            __syncwarp();

            // warp-private activation: 32 samples x 32 neurons; lane = row
            int row = wm * 32 + lane;
            float zc[8][4];
#pragma unroll
            for (int i = 0; i < 8; i++) {
                float4 t4 = *(const float4*)(sm + SM_F32 + row * FROWB + (col0 + i*4) * 4);
                zc[i][0] = t4.x; zc[i][1] = t4.y; zc[i][2] = t4.z; zc[i][3] = t4.w;
            }
#pragma unroll
            for (int i = 0; i < 8; i++)
#pragma unroll
                for (int j = 0; j < 4; j++)
                    zc[i][j] = 0.5f * __sinf(TWO_PI * (zc[i][j] + s_bh[l*128 + col0 + i*4 + j]));
            if (l == NLAY-1) {
#pragma unroll
                for (int i = 0; i < 8; i++)
                    *(float4*)(sm + SM_F32 + row * FROWB + (col0 + i*4) * 4)
                        = make_float4(zc[i][0], zc[i][1], zc[i][2], zc[i][3]);
            } else {
                __syncthreads();
#pragma unroll
                for (int i = 0; i < 8; i++) write_h4(sm, row, col0 + i*4, zc[i]);
            }
        }
    }
    __syncthreads();

    // ---- output layer + losses ----
    if (!is_b) {
        if (tid < 96) {
            int s = tid / NCP, c = tid % NCP;
            if (c < NCU) {
                float a0 = 0, a1 = 0, a2 = 0, a3 = 0;
                const float* hr = (const float*)(sm + SM_F32 + tid * FROWB);
                for (int k = 0; k < D; k++) {
                    float h = hr[k];
                    a0 += h * s_Wo[k*4+0];
                    a1 += h * s_Wo[k*4+1];
                    a2 += h * s_Wo[k*4+2];
                    a3 += h * s_Wo[k*4+3];
                }
                if (c == 0) { a0 += s_bo[0]; a1 += s_bo[1]; a2 += s_bo[2]; a3 += s_bo[3]; }
                s_yc[(s*NCU + c)*4 + 0] = a0;
                s_yc[(s*NCU + c)*4 + 1] = a1;
                s_yc[(s*NCU + c)*4 + 2] = a2;
                s_yc[(s*NCU + c)*4 + 3] = a3;
            }
        }
        __syncthreads();
        if (tid < 4) {
            const int s = tid;
            const int s2c[4][4] = { {0,5,6,7}, {5,8,9,10}, {6,9,11,12}, {7,10,12,13} };
            auto YC = [&](int c, int o) { return s_yc[(s*NCU + c)*4 + o]; };
            auto Hc = [&](int o, int i, int j) { return YC(s2c[i][j], o); };
            auto Gc = [&](int o, int a, int b2) { return YC(14 + (b2-1)*3 + (a-1), o); };
            auto J  = [&](int o, int i) { return YC(1+i, o); };

            float u = YC(0,0), v = YC(0,1), wv = YC(0,2);
            float u_x=J(0,1), u_y=J(0,2), u_z=J(0,3);
            float v_x=J(1,1), v_y=J(1,2), v_z=J(1,3);
            float w_x=J(2,1), w_y=J(2,2), w_z=J(2,3);
            float T_t=J(3,0), T_x=J(3,1), T_y=J(3,2), T_z=J(3,3);

            float om_x = w_y - v_z, om_y = u_z - w_x, om_z = v_x - u_y;

            float NSE_u = Hc(2,2,0) - Hc(1,3,0)
                        + u*(Hc(2,2,1)-Hc(1,3,1)) + v*(Hc(2,2,2)-Hc(1,3,2)) + wv*(Hc(2,2,3)-Hc(1,3,3))
                        - om_x*u_x - om_y*u_y - om_z*u_z
                        - S_CONST*( Gc(2,2,1)-Gc(1,3,1) + Gc(2,2,2)-Gc(1,3,2) + Gc(2,2,3)-Gc(1,3,3) )
                        - T_y;
            float NSE_v = Hc(0,3,0) - Hc(2,1,0)
                        + u*(Hc(0,3,1)-Hc(2,1,1)) + v*(Hc(0,3,2)-Hc(2,1,2)) + wv*(Hc(0,3,3)-Hc(2,1,3))
                        - om_x*v_x - om_y*v_y - om_z*v_z
                        - S_CONST*( Gc(0,3,1)-Gc(2,1,1) + Gc(0,3,2)-Gc(2,1,2) + Gc(0,3,3)-Gc(2,1,3) )
                        + T_x;
            float NSE_w = Hc(1,1,0) - Hc(0,2,0)
                        + u*(Hc(1,1,1)-Hc(0,2,1)) + v*(Hc(1,1,2)-Hc(0,2,2)) + wv*(Hc(1,1,3)-Hc(0,2,3))
                        - om_x*w_x - om_y*w_y - om_z*w_z
                        - S_CONST*( Gc(1,1,1)-Gc(0,2,1) + Gc(1,1,2)-Gc(0,2,2) + Gc(1,1,3)-Gc(0,2,3) );
            float EE = T_t + u*T_x + v*T_y + wv*T_z
                     - KAPPA*( Hc(3,1,1) + Hc(3,2,2) + Hc(3,3,3) );

            float ld = 0.0f;
#pragma unroll
            for (int o = 0; o < 3; o++) {
                float dd = YC(0,o) - s_yt[s*4 + o];
                ld += dd*dd;
            }
            float conti = u_x + v_y + w_z;
            s_ls[s*4+0] = ld;
            s_ls[s*4+1] = conti*conti;
            s_ls[s*4+2] = NSE_u*NSE_u + NSE_v*NSE_v + NSE_w*NSE_w;
            s_ls[s*4+3] = EE*EE;
        }
        __syncthreads();
        if (tid == 0) {
            float a0=0, a1=0, a2=0, a3=0;
            for (int s = 0; s < 4; s++) {
                a0 += s_ls[s*4+0]; a1 += s_ls[s*4+1];
                a2 += s_ls[s*4+2]; a3 += s_ls[s*4+3];
            }
            g_part[bid*4+0] = a0; g_part[bid*4+1] = a1;
            g_part[bid*4+2] = a2; g_part[bid*4+3] = a3;
        }
    } else {
        if (tid < 64) {
            float acc = 0.0f;
            const float* hr = (const float*)(sm + SM_F32 + tid * FROWB);
            for (int k = 0; k < D; k++)
                acc += hr[k] * s_Wo[k*4+3];
            float T = acc + s_bo[3];
            float Tt = (s_x[tid*4+3] == 0.0f) ? 0.5f : -0.5f;
            float dd = Tt - T;
            s_red[tid] = dd * dd;
        }
        __syncthreads();
        if (tid == 0) {
            float a = 0.0f;
            for (int i = 0; i < 64; i++) a += s_red[i];
            g_tbpart[bid - NMAIN] = a;
        }
    }

    // ---- last-CTA final reduction ----
    __syncthreads();
    if (tid == 0) {
        __threadfence();
        unsigned int old = atomicAdd(&g_done, 1u);
        *(unsigned int*)(sm + SM_FLAG) = (old == NCTA - 1) ? 1u : 0u;
    }
    __syncthreads();
    if (*(volatile unsigned int*)(sm + SM_FLAG)) {
        double v[5] = {0, 0, 0, 0, 0};
        for (int i = tid; i < NMAIN; i += NTHR) {
            v[0] += (double)g_part[i*4+0];
            v[1] += (double)g_part[i*4+1];
            v[2] += (double)g_part[i*4+2];
            v[3] += (double)g_part[i*4+3];
        }
        if (tid < NBND) v[4] = (double)g_tbpart[tid];
#pragma unroll
        for (int o = 16; o; o >>= 1)
#pragma unroll
            for (int q = 0; q < 5; q++)
                v[q] += __shfl_down_sync(0xFFFFFFFFu, v[q], o);
        double* sacc = (double*)(sm + SM_YC);
        if (lane == 0)
#pragma unroll
            for (int q = 0; q < 5; q++) sacc[w*5 + q] = v[q];
        __syncthreads();
        if (tid == 0) {
            double s5[5] = {0, 0, 0, 0, 0};
            for (int ww = 0; ww < 8; ww++)
#pragma unroll
                for (int q = 0; q < 5; q++) s5[q] += sacc[ww*5 + q];
            double Nf = (double)N_SAMP;
            out[0] = (float)(s5[0]/(3.0*Nf) + s5[1]/Nf + s5[2]/(3.0*Nf) + s5[3]/Nf + s5[4]/Nf);
            g_done = 0;   // reset for next graph replay
        }
    }
}

// ------- launch -------
extern "C" void kernel_launch(void* const* d_in, const int* in_sizes, int n_in,
                              void* d_out, int out_size) {
    const float* inputs = (const float*)d_in[0];
    const float* y_true = (const float*)d_in[1];
    const float* Win    = (const float*)d_in[2];
    const float* bin    = (const float*)d_in[3];
    const float* Wh     = (const float*)d_in[4];
    const float* bh     = (const float*)d_in[5];
    const float* Wo     = (const float*)d_in[6];
    const float* bo     = (const float*)d_in[7];
    float* out = (float*)d_out;

    cudaFuncSetAttribute(pinn_tc, cudaFuncAttributeMaxDynamicSharedMemorySize, SMEM_TOTAL);

    pinn_prep<<<336, 256>>>(Wh);
    pinn_tc<<<NCTA, NTHR, SMEM_TOTAL>>>(inputs, y_true, Win, bin, bh, Wo, bo, out);
}